// round 2
// baseline (speedup 1.0000x reference)
#include <cuda_runtime.h>
#include <cuda_bf16.h>

#define BM 64
#define BN 64
#define DH 64
#define QS_STRIDE 68   // padded, float4-aligned (272B)
#define PS_STRIDE 65   // padded, scalar access

// Flash-attention, fp32 SIMT baseline.
// Grid: (Lq/BM, B). Block: 256 threads = 16x16 (tx, ty).
// Thread owns a 4x4 fragment of the 64x64 S tile (rows 4*ty+i, cols 4*tx+j)
// and a 4x4 fragment of the 64x64 O tile (rows 4*ty+i, dcols 4*tx+j).
__global__ __launch_bounds__(256, 2)
void fa_fp32_kernel(const float* __restrict__ Q, const float* __restrict__ K,
                    const float* __restrict__ V, const int* __restrict__ vlen,
                    float* __restrict__ O, int Lq, int Lk)
{
    extern __shared__ float sm[];
    float* Qs = sm;                       // [DH][QS_STRIDE]  d-major (transposed)
    float* Ks = Qs + DH * QS_STRIDE;      // [DH][QS_STRIDE]  d-major (transposed)
    float* Vs = Ks + DH * QS_STRIDE;      // [BN][QS_STRIDE]  natural (k-row major)
    float* Ps = Vs + BN * QS_STRIDE;      // [BN][PS_STRIDE]  k-major, m minor

    const int b  = blockIdx.y;
    const int q0 = blockIdx.x * BM;
    const int t  = threadIdx.x;
    const int tx = t & 15;
    const int ty = t >> 4;

    int vl = vlen[b];
    if (vl < 1) vl = 1;
    if (vl > Lk) vl = Lk;                 // defensive clamp: never read OOB
    const int ntiles = (vl + BN - 1) / BN;

    const float scale = 0.125f;  // 1/sqrt(64)

    const float* Qb = Q + ((size_t)b * Lq + q0) * DH;
    const float* Kb = K + (size_t)b * Lk * DH;
    const float* Vb = V + (size_t)b * Lk * DH;

    // ---- load Q tile once, transposed + pre-scaled ----
    {
        int r = t >> 2, qb = t & 3;
        #pragma unroll
        for (int s2 = 0; s2 < 4; s2++) {
            int d = 4 * qb + 16 * s2;
            float4 v = *(const float4*)(Qb + (size_t)r * DH + d);
            Qs[(d + 0) * QS_STRIDE + r] = v.x * scale;
            Qs[(d + 1) * QS_STRIDE + r] = v.y * scale;
            Qs[(d + 2) * QS_STRIDE + r] = v.z * scale;
            Qs[(d + 3) * QS_STRIDE + r] = v.w * scale;
        }
    }

    float o[4][4];
    float m[4], l[4];
    #pragma unroll
    for (int i = 0; i < 4; i++) {
        m[i] = -1e30f; l[i] = 0.f;
        #pragma unroll
        for (int j = 0; j < 4; j++) o[i][j] = 0.f;
    }

    __syncthreads();

    for (int kt = 0; kt < ntiles; kt++) {
        const int n0 = kt * BN;

        // ---- load K (transposed) + V (natural) tiles ----
        {
            int r = t >> 2, qb = t & 3;
            #pragma unroll
            for (int s2 = 0; s2 < 4; s2++) {
                int d = 4 * qb + 16 * s2;
                float4 kv = *(const float4*)(Kb + (size_t)(n0 + r) * DH + d);
                Ks[(d + 0) * QS_STRIDE + r] = kv.x;
                Ks[(d + 1) * QS_STRIDE + r] = kv.y;
                Ks[(d + 2) * QS_STRIDE + r] = kv.z;
                Ks[(d + 3) * QS_STRIDE + r] = kv.w;
                float4 vv = *(const float4*)(Vb + (size_t)(n0 + r) * DH + d);
                *(float4*)(Vs + r * QS_STRIDE + d) = vv;
            }
        }
        __syncthreads();

        // ---- S = (Q * scale) K^T : 4x4 fragment per thread ----
        float s[4][4];
        #pragma unroll
        for (int i = 0; i < 4; i++)
            #pragma unroll
            for (int j = 0; j < 4; j++) s[i][j] = 0.f;

        #pragma unroll 8
        for (int k = 0; k < DH; k++) {
            float4 aa = *(const float4*)(Qs + k * QS_STRIDE + 4 * ty);
            float4 bb = *(const float4*)(Ks + k * QS_STRIDE + 4 * tx);
            float av[4] = {aa.x, aa.y, aa.z, aa.w};
            float bv[4] = {bb.x, bb.y, bb.z, bb.w};
            #pragma unroll
            for (int i = 0; i < 4; i++)
                #pragma unroll
                for (int j = 0; j < 4; j++)
                    s[i][j] = fmaf(av[i], bv[j], s[i][j]);
        }

        // ---- key-length mask (only last tile can be partial) ----
        if (n0 + BN > vl) {
            #pragma unroll
            for (int j = 0; j < 4; j++) {
                if (n0 + 4 * tx + j >= vl) {
                    #pragma unroll
                    for (int i = 0; i < 4; i++) s[i][j] = -1e6f;
                }
            }
        }

        // ---- online softmax: row reductions across the 16-lane tx group ----
        #pragma unroll
        for (int i = 0; i < 4; i++) {
            float tm = fmaxf(fmaxf(s[i][0], s[i][1]), fmaxf(s[i][2], s[i][3]));
            #pragma unroll
            for (int off = 8; off; off >>= 1)
                tm = fmaxf(tm, __shfl_xor_sync(0xffffffffu, tm, off));
            float mn = fmaxf(m[i], tm);
            float rs = 0.f;
            #pragma unroll
            for (int j = 0; j < 4; j++) {
                float p = __expf(s[i][j] - mn);
                Ps[(4 * tx + j) * PS_STRIDE + 4 * ty + i] = p;
                rs += p;
            }
            #pragma unroll
            for (int off = 8; off; off >>= 1)
                rs += __shfl_xor_sync(0xffffffffu, rs, off);
            float corr = __expf(m[i] - mn);
            l[i] = l[i] * corr + rs;
            m[i] = mn;
            #pragma unroll
            for (int j = 0; j < 4; j++) o[i][j] *= corr;
        }
        __syncthreads();

        // ---- O += P V : 4x4 fragment per thread ----
        #pragma unroll 8
        for (int k = 0; k < BN; k++) {
            float4 bb = *(const float4*)(Vs + k * QS_STRIDE + 4 * tx);
            float bv[4] = {bb.x, bb.y, bb.z, bb.w};
            float a0 = Ps[k * PS_STRIDE + 4 * ty + 0];
            float a1 = Ps[k * PS_STRIDE + 4 * ty + 1];
            float a2 = Ps[k * PS_STRIDE + 4 * ty + 2];
            float a3 = Ps[k * PS_STRIDE + 4 * ty + 3];
            #pragma unroll
            for (int j = 0; j < 4; j++) {
                o[0][j] = fmaf(a0, bv[j], o[0][j]);
                o[1][j] = fmaf(a1, bv[j], o[1][j]);
                o[2][j] = fmaf(a2, bv[j], o[2][j]);
                o[3][j] = fmaf(a3, bv[j], o[3][j]);
            }
        }
        __syncthreads();
    }

    // ---- finalize: divide by softmax denominator, write out ----
    #pragma unroll
    for (int i = 0; i < 4; i++) {
        float inv = 1.f / l[i];
        float4 r;
        r.x = o[i][0] * inv;
        r.y = o[i][1] * inv;
        r.z = o[i][2] * inv;
        r.w = o[i][3] * inv;
        *(float4*)(O + ((size_t)b * Lq + q0 + 4 * ty + i) * DH + 4 * tx) = r;
    }
}

extern "C" void kernel_launch(void* const* d_in, const int* in_sizes, int n_in,
                              void* d_out, int out_size)
{
    const float* Q  = (const float*)d_in[0];
    const float* K  = (const float*)d_in[1];
    const float* V  = (const float*)d_in[2];
    const int*   vl = (const int*)d_in[3];   // int64 in reference, int32 in harness
    float*       O  = (float*)d_out;

    const int B  = in_sizes[3];
    const int Lq = in_sizes[0] / (B * DH);
    const int Lk = in_sizes[1] / (B * DH);

    const size_t smem = (size_t)(3 * DH * QS_STRIDE + BN * PS_STRIDE) * sizeof(float);
    cudaFuncSetAttribute(fa_fp32_kernel,
                         cudaFuncAttributeMaxDynamicSharedMemorySize, (int)smem);

    dim3 grid(Lq / BM, B);
    fa_fp32_kernel<<<grid, 256, smem>>>(Q, K, V, vl, O, Lq, Lk);
}

// round 4
// speedup vs baseline: 2.6397x; 2.6397x over previous
#include <cuda_runtime.h>
#include <cuda_bf16.h>
#include <cstdint>

#define DH 64
#define BM 128
#define BN 64
#define SKB 144          // smem row stride bytes (72 bf16) -> ldmatrix conflict-free

#define SM_QHI 0
#define SM_QLO (SM_QHI + BM*SKB)
#define SM_KHI (SM_QLO + BM*SKB)
#define SM_KLO (SM_KHI + BN*SKB)
#define SM_VHI (SM_KLO + BN*SKB)
#define SM_VLO (SM_VHI + BN*SKB)
#define SM_TOTAL (SM_VLO + BN*SKB)   // 73728 B

static __device__ __forceinline__ uint32_t smem_u32(const void* p){
    uint32_t a;
    asm("{ .reg .u64 t; cvta.to.shared.u64 t, %1; cvt.u32.u64 %0, t; }" : "=r"(a) : "l"(p));
    return a;
}
static __device__ __forceinline__ uint32_t pk(__nv_bfloat16 a, __nv_bfloat16 b){
    __nv_bfloat162 t; t.x = a; t.y = b;
    return *reinterpret_cast<uint32_t*>(&t);
}
// split 8 floats into hi/lo bf16 (hi = rn(f), lo = rn(f - hi)), packed 8x bf16 per uint4
static __device__ __forceinline__ void split8(const float* f, uint4& hi, uint4& lo){
    uint32_t h[4], l[4];
    #pragma unroll
    for (int i = 0; i < 4; i++){
        __nv_bfloat16 h0 = __float2bfloat16(f[2*i]);
        __nv_bfloat16 h1 = __float2bfloat16(f[2*i+1]);
        __nv_bfloat16 l0 = __float2bfloat16(f[2*i]   - __bfloat162float(h0));
        __nv_bfloat16 l1 = __float2bfloat16(f[2*i+1] - __bfloat162float(h1));
        h[i] = pk(h0, h1); l[i] = pk(l0, l1);
    }
    hi = make_uint4(h[0], h[1], h[2], h[3]);
    lo = make_uint4(l[0], l[1], l[2], l[3]);
}
static __device__ __forceinline__ void ldsm4(uint32_t* r, uint32_t a){
    asm volatile("ldmatrix.sync.aligned.m8n8.x4.shared.b16 {%0,%1,%2,%3}, [%4];"
                 : "=r"(r[0]), "=r"(r[1]), "=r"(r[2]), "=r"(r[3]) : "r"(a));
}
static __device__ __forceinline__ void ldsm4t(uint32_t* r, uint32_t a){
    asm volatile("ldmatrix.sync.aligned.m8n8.x4.trans.shared.b16 {%0,%1,%2,%3}, [%4];"
                 : "=r"(r[0]), "=r"(r[1]), "=r"(r[2]), "=r"(r[3]) : "r"(a));
}
static __device__ __forceinline__ void mma16816(float* d, const uint32_t* a, uint32_t b0, uint32_t b1){
    asm volatile("mma.sync.aligned.m16n8k16.row.col.f32.bf16.bf16.f32 "
                 "{%0,%1,%2,%3}, {%4,%5,%6,%7}, {%8,%9}, {%0,%1,%2,%3};"
                 : "+f"(d[0]), "+f"(d[1]), "+f"(d[2]), "+f"(d[3])
                 : "r"(a[0]), "r"(a[1]), "r"(a[2]), "r"(a[3]), "r"(b0), "r"(b1));
}

__global__ __launch_bounds__(256, 1)
void fa_mma_kernel(const float* __restrict__ Q, const float* __restrict__ K,
                   const float* __restrict__ V, const int* __restrict__ vlen,
                   float* __restrict__ O, int Lq, int Lk)
{
    extern __shared__ char smem[];
    const uint32_t sb = smem_u32(smem);
    const int t  = threadIdx.x;
    const int w  = t >> 5;
    const int ln = t & 31;
    const int g  = ln >> 2;       // row group within 16-row warp tile
    const int tg = ln & 3;        // col pair selector
    const int b  = blockIdx.y;
    const int q0 = blockIdx.x * BM;

    int vl = vlen[b];
    if (vl < 1) vl = 1;
    if (vl > Lk) vl = Lk;
    const int ntiles = (vl + BN - 1) / BN;

    const float* Qb = Q + ((size_t)b * Lq + q0) * DH;
    const float* Kb = K + (size_t)b * Lk * DH;
    const float* Vb = V + (size_t)b * Lk * DH;

    // ---- Q -> smem, pre-scaled, bf16 hi/lo split ----
    {
        int r = t >> 1, h = t & 1;
        const float* qp = Qb + (size_t)r * DH + h * 32;
        float f[32];
        #pragma unroll
        for (int i = 0; i < 8; i++) *(float4*)(f + 4*i) = *(const float4*)(qp + 4*i);
        #pragma unroll
        for (int i = 0; i < 32; i++) f[i] *= 0.125f;   // 1/sqrt(64)
        #pragma unroll
        for (int c = 0; c < 4; c++){
            uint4 hi, lo; split8(f + 8*c, hi, lo);
            int off = r * SKB + (h*4 + c) * 16;
            *(uint4*)(smem + SM_QHI + off) = hi;
            *(uint4*)(smem + SM_QLO + off) = lo;
        }
    }
    __syncthreads();

    // ---- Q A-fragments (kept in registers for the whole kernel) ----
    uint32_t qhi[4][4], qlo[4][4];
    {
        uint32_t rowoff = (uint32_t)(16*w + (ln & 15)) * SKB + (uint32_t)(ln >> 4) * 16;
        #pragma unroll
        for (int ks = 0; ks < 4; ks++){
            ldsm4(qhi[ks], sb + SM_QHI + rowoff + ks * 32);
            ldsm4(qlo[ks], sb + SM_QLO + rowoff + ks * 32);
        }
    }

    float oc[8][4];
    #pragma unroll
    for (int nt = 0; nt < 8; nt++)
        #pragma unroll
        for (int j = 0; j < 4; j++) oc[nt][j] = 0.f;
    float lsum0 = 0.f, lsum1 = 0.f;

    // ---- prefetch tile 0 ----
    const int r4 = t >> 2, qq = t & 3;
    float4 kf[4], vf[4];
    {
        const float* kp = Kb + (size_t)r4 * DH + qq * 16;
        const float* vp = Vb + (size_t)r4 * DH + qq * 16;
        #pragma unroll
        for (int i = 0; i < 4; i++){ kf[i] = *(const float4*)(kp + 4*i); vf[i] = *(const float4*)(vp + 4*i); }
    }

    for (int kt = 0; kt < ntiles; kt++){
        const int n0 = kt * BN;

        __syncthreads();   // prev tile's ldmatrix reads done
        // ---- store K/V tile (hi/lo split) ----
        {
            int off = r4 * SKB + qq * 32;
            float fk[8];
            *(float4*)(fk)     = kf[0]; *(float4*)(fk + 4) = kf[1];
            uint4 hi, lo; split8(fk, hi, lo);
            *(uint4*)(smem + SM_KHI + off) = hi; *(uint4*)(smem + SM_KLO + off) = lo;
            *(float4*)(fk)     = kf[2]; *(float4*)(fk + 4) = kf[3];
            split8(fk, hi, lo);
            *(uint4*)(smem + SM_KHI + off + 16) = hi; *(uint4*)(smem + SM_KLO + off + 16) = lo;

            *(float4*)(fk)     = vf[0]; *(float4*)(fk + 4) = vf[1];
            split8(fk, hi, lo);
            *(uint4*)(smem + SM_VHI + off) = hi; *(uint4*)(smem + SM_VLO + off) = lo;
            *(float4*)(fk)     = vf[2]; *(float4*)(fk + 4) = vf[3];
            split8(fk, hi, lo);
            *(uint4*)(smem + SM_VHI + off + 16) = hi; *(uint4*)(smem + SM_VLO + off + 16) = lo;
        }
        __syncthreads();

        // ---- prefetch next tile ----
        if (kt + 1 < ntiles){
            const float* kp = Kb + (size_t)((kt+1)*BN + r4) * DH + qq * 16;
            const float* vp = Vb + (size_t)((kt+1)*BN + r4) * DH + qq * 16;
            #pragma unroll
            for (int i = 0; i < 4; i++){ kf[i] = *(const float4*)(kp + 4*i); vf[i] = *(const float4*)(vp + 4*i); }
        }

        // ---- S = Q K^T (split precision, 3 passes) ----
        float sc[8][4];
        #pragma unroll
        for (int nt = 0; nt < 8; nt++){
            #pragma unroll
            for (int j = 0; j < 4; j++) sc[nt][j] = 0.f;
            uint32_t kh[8], kl[8];
            uint32_t base = (uint32_t)(8*nt + (ln & 7)) * SKB
                          + (uint32_t)((ln >> 3) & 1) * 16
                          + (uint32_t)(ln >> 4) * 32;
            ldsm4(kh + 0, sb + SM_KHI + base);
            ldsm4(kh + 4, sb + SM_KHI + base + 64);
            ldsm4(kl + 0, sb + SM_KLO + base);
            ldsm4(kl + 4, sb + SM_KLO + base + 64);
            #pragma unroll
            for (int ks = 0; ks < 4; ks++){
                mma16816(sc[nt], qhi[ks], kh[2*ks], kh[2*ks+1]);
                mma16816(sc[nt], qhi[ks], kl[2*ks], kl[2*ks+1]);
                mma16816(sc[nt], qlo[ks], kh[2*ks], kh[2*ks+1]);
            }
        }

        // ---- epilogue: P = exp(S) with key-length mask; pack A-frags ----
        uint32_t phi[4][4], plo[4][4];
        #pragma unroll
        for (int nt = 0; nt < 8; nt++){
            int c0 = n0 + nt*8 + 2*tg;
            float e0 = (c0     < vl) ? __expf(sc[nt][0]) : 0.f;
            float e1 = (c0 + 1 < vl) ? __expf(sc[nt][1]) : 0.f;
            float e2 = (c0     < vl) ? __expf(sc[nt][2]) : 0.f;
            float e3 = (c0 + 1 < vl) ? __expf(sc[nt][3]) : 0.f;
            lsum0 += e0 + e1;
            lsum1 += e2 + e3;
            __nv_bfloat16 h0 = __float2bfloat16(e0), h1 = __float2bfloat16(e1);
            __nv_bfloat16 h2 = __float2bfloat16(e2), h3 = __float2bfloat16(e3);
            __nv_bfloat16 x0 = __float2bfloat16(e0 - __bfloat162float(h0));
            __nv_bfloat16 x1 = __float2bfloat16(e1 - __bfloat162float(h1));
            __nv_bfloat16 x2 = __float2bfloat16(e2 - __bfloat162float(h2));
            __nv_bfloat16 x3 = __float2bfloat16(e3 - __bfloat162float(h3));
            int j = nt >> 1, hf = (nt & 1) * 2;
            phi[j][hf + 0] = pk(h0, h1); phi[j][hf + 1] = pk(h2, h3);
            plo[j][hf + 0] = pk(x0, x1); plo[j][hf + 1] = pk(x2, x3);
        }

        // ---- O += P V (split precision, 3 passes) ----
        #pragma unroll
        for (int nt = 0; nt < 8; nt++){
            uint32_t vh[8], vr[8];
            uint32_t base = (uint32_t)ln * SKB + (uint32_t)nt * 16;
            ldsm4t(vh + 0, sb + SM_VHI + base);
            ldsm4t(vh + 4, sb + SM_VHI + base + 32u * SKB);
            ldsm4t(vr + 0, sb + SM_VLO + base);
            ldsm4t(vr + 4, sb + SM_VLO + base + 32u * SKB);
            #pragma unroll
            for (int ks = 0; ks < 4; ks++){
                mma16816(oc[nt], phi[ks], vh[2*ks], vh[2*ks+1]);
                mma16816(oc[nt], phi[ks], vr[2*ks], vr[2*ks+1]);
                mma16816(oc[nt], plo[ks], vh[2*ks], vh[2*ks+1]);
            }
        }
    }

    // ---- reduce row sums across the 4 lanes of each quad ----
    lsum0 += __shfl_xor_sync(0xffffffffu, lsum0, 1);
    lsum0 += __shfl_xor_sync(0xffffffffu, lsum0, 2);
    lsum1 += __shfl_xor_sync(0xffffffffu, lsum1, 1);
    lsum1 += __shfl_xor_sync(0xffffffffu, lsum1, 2);
    const float inv0 = 1.f / lsum0;
    const float inv1 = 1.f / lsum1;

    // ---- normalize + store ----
    const int row0 = q0 + 16*w + g;
    float* O0 = O + ((size_t)b * Lq + row0) * DH;
    float* O1 = O0 + 8 * DH;
    #pragma unroll
    for (int nt = 0; nt < 8; nt++){
        float2 a, c;
        a.x = oc[nt][0] * inv0; a.y = oc[nt][1] * inv0;
        c.x = oc[nt][2] * inv1; c.y = oc[nt][3] * inv1;
        *(float2*)(O0 + nt*8 + 2*tg) = a;
        *(float2*)(O1 + nt*8 + 2*tg) = c;
    }
}

extern "C" void kernel_launch(void* const* d_in, const int* in_sizes, int n_in,
                              void* d_out, int out_size)
{
    const float* Q  = (const float*)d_in[0];
    const float* K  = (const float*)d_in[1];
    const float* V  = (const float*)d_in[2];
    const int*   vl = (const int*)d_in[3];
    float*       O  = (float*)d_out;

    const int B  = in_sizes[3];
    const int Lq = in_sizes[0] / (B * DH);
    const int Lk = in_sizes[1] / (B * DH);

    cudaFuncSetAttribute(fa_mma_kernel,
                         cudaFuncAttributeMaxDynamicSharedMemorySize, SM_TOTAL);

    dim3 grid(Lq / BM, B);
    fa_mma_kernel<<<grid, 256, SM_TOTAL>>>(Q, K, V, vl, O, Lq, Lk);
}

// round 5
// speedup vs baseline: 3.8491x; 1.4581x over previous
#include <cuda_runtime.h>
#include <cuda_bf16.h>
#include <cstdint>

#define DH 64
#define BM 128
#define BN 64
#define SKB 144          // smem row stride bytes (72 bf16) -> ldmatrix conflict-free

#define SM_QHI 0
#define SM_QLO (SM_QHI + BM*SKB)
#define SM_KHI (SM_QLO + BM*SKB)
#define SM_KLO (SM_KHI + BN*SKB)
#define SM_VHI (SM_KLO + BN*SKB)
#define SM_VLO (SM_VHI + BN*SKB)
#define SM_TOTAL (SM_VLO + BN*SKB)   // 73728 B

#define MAXROWS 16384                 // B*Lq capacity of scratch
#define NCH_MAX 4

// split-KV scratch: unnormalized O partials + l partials (static device arrays)
__device__ float g_Opart[(size_t)NCH_MAX * MAXROWS * DH];
__device__ float g_lpart[(size_t)NCH_MAX * MAXROWS];

static __device__ __forceinline__ uint32_t smem_u32(const void* p){
    uint32_t a;
    asm("{ .reg .u64 t; cvta.to.shared.u64 t, %1; cvt.u32.u64 %0, t; }" : "=r"(a) : "l"(p));
    return a;
}
static __device__ __forceinline__ uint32_t pk(__nv_bfloat16 a, __nv_bfloat16 b){
    __nv_bfloat162 t; t.x = a; t.y = b;
    return *reinterpret_cast<uint32_t*>(&t);
}
static __device__ __forceinline__ void split8(const float* f, uint4& hi, uint4& lo){
    uint32_t h[4], l[4];
    #pragma unroll
    for (int i = 0; i < 4; i++){
        __nv_bfloat16 h0 = __float2bfloat16(f[2*i]);
        __nv_bfloat16 h1 = __float2bfloat16(f[2*i+1]);
        __nv_bfloat16 l0 = __float2bfloat16(f[2*i]   - __bfloat162float(h0));
        __nv_bfloat16 l1 = __float2bfloat16(f[2*i+1] - __bfloat162float(h1));
        h[i] = pk(h0, h1); l[i] = pk(l0, l1);
    }
    hi = make_uint4(h[0], h[1], h[2], h[3]);
    lo = make_uint4(l[0], l[1], l[2], l[3]);
}
static __device__ __forceinline__ void ldsm4(uint32_t* r, uint32_t a){
    asm volatile("ldmatrix.sync.aligned.m8n8.x4.shared.b16 {%0,%1,%2,%3}, [%4];"
                 : "=r"(r[0]), "=r"(r[1]), "=r"(r[2]), "=r"(r[3]) : "r"(a));
}
static __device__ __forceinline__ void ldsm4t(uint32_t* r, uint32_t a){
    asm volatile("ldmatrix.sync.aligned.m8n8.x4.trans.shared.b16 {%0,%1,%2,%3}, [%4];"
                 : "=r"(r[0]), "=r"(r[1]), "=r"(r[2]), "=r"(r[3]) : "r"(a));
}
static __device__ __forceinline__ void mma16816(float* d, const uint32_t* a, uint32_t b0, uint32_t b1){
    asm volatile("mma.sync.aligned.m16n8k16.row.col.f32.bf16.bf16.f32 "
                 "{%0,%1,%2,%3}, {%4,%5,%6,%7}, {%8,%9}, {%0,%1,%2,%3};"
                 : "+f"(d[0]), "+f"(d[1]), "+f"(d[2]), "+f"(d[3])
                 : "r"(a[0]), "r"(a[1]), "r"(a[2]), "r"(a[3]), "r"(b0), "r"(b1));
}

// ---------------- Phase 1: partial attention over one key chunk ----------------
__global__ __launch_bounds__(256, 1)
void fa_part_kernel(const float* __restrict__ Q, const float* __restrict__ K,
                    const float* __restrict__ V, const int* __restrict__ vlen,
                    int Lq, int Lk, int ck)
{
    extern __shared__ char smem[];
    const uint32_t sb = smem_u32(smem);
    const int t  = threadIdx.x;
    const int w  = t >> 5;
    const int ln = t & 31;
    const int g  = ln >> 2;
    const int tg = ln & 3;
    const int b  = blockIdx.y;
    const int q0 = blockIdx.x * BM;
    const int c  = blockIdx.z;

    int vl = vlen[b];
    if (vl < 1) vl = 1;
    if (vl > Lk) vl = Lk;

    const int cstart = c * ck;
    if (cstart >= vl) return;                       // empty chunk
    const int kend   = (cstart + ck < vl) ? cstart + ck : vl;
    const int ntiles = (kend - cstart + BN - 1) / BN;

    const int B_ = gridDim.y;
    const int R  = B_ * Lq;

    const float* Qb = Q + ((size_t)b * Lq + q0) * DH;
    const float* Kb = K + ((size_t)b * Lk + cstart) * DH;
    const float* Vb = V + ((size_t)b * Lk + cstart) * DH;

    // ---- Q -> smem, pre-scaled, bf16 hi/lo split ----
    {
        int r = t >> 1, h = t & 1;
        const float* qp = Qb + (size_t)r * DH + h * 32;
        float f[32];
        #pragma unroll
        for (int i = 0; i < 8; i++) *(float4*)(f + 4*i) = *(const float4*)(qp + 4*i);
        #pragma unroll
        for (int i = 0; i < 32; i++) f[i] *= 0.125f;   // 1/sqrt(64)
        #pragma unroll
        for (int cc = 0; cc < 4; cc++){
            uint4 hi, lo; split8(f + 8*cc, hi, lo);
            int off = r * SKB + (h*4 + cc) * 16;
            *(uint4*)(smem + SM_QHI + off) = hi;
            *(uint4*)(smem + SM_QLO + off) = lo;
        }
    }
    __syncthreads();

    // ---- Q A-fragments ----
    uint32_t qhi[4][4], qlo[4][4];
    {
        uint32_t rowoff = (uint32_t)(16*w + (ln & 15)) * SKB + (uint32_t)(ln >> 4) * 16;
        #pragma unroll
        for (int ks = 0; ks < 4; ks++){
            ldsm4(qhi[ks], sb + SM_QHI + rowoff + ks * 32);
            ldsm4(qlo[ks], sb + SM_QLO + rowoff + ks * 32);
        }
    }

    float oc[8][4];
    #pragma unroll
    for (int nt = 0; nt < 8; nt++)
        #pragma unroll
        for (int j = 0; j < 4; j++) oc[nt][j] = 0.f;
    float lsum0 = 0.f, lsum1 = 0.f;

    const int r4 = t >> 2, qq = t & 3;
    float4 kf[4], vf[4];
    {
        const float* kp = Kb + (size_t)r4 * DH + qq * 16;
        const float* vp = Vb + (size_t)r4 * DH + qq * 16;
        #pragma unroll
        for (int i = 0; i < 4; i++){ kf[i] = *(const float4*)(kp + 4*i); vf[i] = *(const float4*)(vp + 4*i); }
    }

    for (int kt = 0; kt < ntiles; kt++){
        const int n0g = cstart + kt * BN;           // global key offset of this tile

        __syncthreads();
        {
            int off = r4 * SKB + qq * 32;
            float fk[8];
            *(float4*)(fk)     = kf[0]; *(float4*)(fk + 4) = kf[1];
            uint4 hi, lo; split8(fk, hi, lo);
            *(uint4*)(smem + SM_KHI + off) = hi; *(uint4*)(smem + SM_KLO + off) = lo;
            *(float4*)(fk)     = kf[2]; *(float4*)(fk + 4) = kf[3];
            split8(fk, hi, lo);
            *(uint4*)(smem + SM_KHI + off + 16) = hi; *(uint4*)(smem + SM_KLO + off + 16) = lo;

            *(float4*)(fk)     = vf[0]; *(float4*)(fk + 4) = vf[1];
            split8(fk, hi, lo);
            *(uint4*)(smem + SM_VHI + off) = hi; *(uint4*)(smem + SM_VLO + off) = lo;
            *(float4*)(fk)     = vf[2]; *(float4*)(fk + 4) = vf[3];
            split8(fk, hi, lo);
            *(uint4*)(smem + SM_VHI + off + 16) = hi; *(uint4*)(smem + SM_VLO + off + 16) = lo;
        }
        __syncthreads();

        if (kt + 1 < ntiles){
            const float* kp = Kb + (size_t)((kt+1)*BN + r4) * DH + qq * 16;
            const float* vp = Vb + (size_t)((kt+1)*BN + r4) * DH + qq * 16;
            #pragma unroll
            for (int i = 0; i < 4; i++){ kf[i] = *(const float4*)(kp + 4*i); vf[i] = *(const float4*)(vp + 4*i); }
        }

        // ---- S = Q K^T (split precision) ----
        float sc[8][4];
        #pragma unroll
        for (int nt = 0; nt < 8; nt++){
            #pragma unroll
            for (int j = 0; j < 4; j++) sc[nt][j] = 0.f;
            uint32_t kh[8], kl[8];
            uint32_t base = (uint32_t)(8*nt + (ln & 7)) * SKB
                          + (uint32_t)((ln >> 3) & 1) * 16
                          + (uint32_t)(ln >> 4) * 32;
            ldsm4(kh + 0, sb + SM_KHI + base);
            ldsm4(kh + 4, sb + SM_KHI + base + 64);
            ldsm4(kl + 0, sb + SM_KLO + base);
            ldsm4(kl + 4, sb + SM_KLO + base + 64);
            #pragma unroll
            for (int ks = 0; ks < 4; ks++){
                mma16816(sc[nt], qhi[ks], kh[2*ks], kh[2*ks+1]);
                mma16816(sc[nt], qhi[ks], kl[2*ks], kl[2*ks+1]);
                mma16816(sc[nt], qlo[ks], kh[2*ks], kh[2*ks+1]);
            }
        }

        // ---- P = exp(S) with key-length mask ----
        uint32_t phi[4][4], plo[4][4];
        #pragma unroll
        for (int nt = 0; nt < 8; nt++){
            int c0 = n0g + nt*8 + 2*tg;
            float e0 = (c0     < vl) ? __expf(sc[nt][0]) : 0.f;
            float e1 = (c0 + 1 < vl) ? __expf(sc[nt][1]) : 0.f;
            float e2 = (c0     < vl) ? __expf(sc[nt][2]) : 0.f;
            float e3 = (c0 + 1 < vl) ? __expf(sc[nt][3]) : 0.f;
            lsum0 += e0 + e1;
            lsum1 += e2 + e3;
            __nv_bfloat16 h0 = __float2bfloat16(e0), h1 = __float2bfloat16(e1);
            __nv_bfloat16 h2 = __float2bfloat16(e2), h3 = __float2bfloat16(e3);
            __nv_bfloat16 x0 = __float2bfloat16(e0 - __bfloat162float(h0));
            __nv_bfloat16 x1 = __float2bfloat16(e1 - __bfloat162float(h1));
            __nv_bfloat16 x2 = __float2bfloat16(e2 - __bfloat162float(h2));
            __nv_bfloat16 x3 = __float2bfloat16(e3 - __bfloat162float(h3));
            int j = nt >> 1, hf = (nt & 1) * 2;
            phi[j][hf + 0] = pk(h0, h1); phi[j][hf + 1] = pk(h2, h3);
            plo[j][hf + 0] = pk(x0, x1); plo[j][hf + 1] = pk(x2, x3);
        }

        // ---- O += P V (split precision) ----
        #pragma unroll
        for (int nt = 0; nt < 8; nt++){
            uint32_t vh[8], vr[8];
            uint32_t base = (uint32_t)ln * SKB + (uint32_t)nt * 16;
            ldsm4t(vh + 0, sb + SM_VHI + base);
            ldsm4t(vh + 4, sb + SM_VHI + base + 32u * SKB);
            ldsm4t(vr + 0, sb + SM_VLO + base);
            ldsm4t(vr + 4, sb + SM_VLO + base + 32u * SKB);
            #pragma unroll
            for (int ks = 0; ks < 4; ks++){
                mma16816(oc[nt], phi[ks], vh[2*ks], vh[2*ks+1]);
                mma16816(oc[nt], phi[ks], vr[2*ks], vr[2*ks+1]);
                mma16816(oc[nt], plo[ks], vh[2*ks], vh[2*ks+1]);
            }
        }
    }

    // ---- reduce row sums across quads ----
    lsum0 += __shfl_xor_sync(0xffffffffu, lsum0, 1);
    lsum0 += __shfl_xor_sync(0xffffffffu, lsum0, 2);
    lsum1 += __shfl_xor_sync(0xffffffffu, lsum1, 1);
    lsum1 += __shfl_xor_sync(0xffffffffu, lsum1, 2);

    // ---- write unnormalized partials to scratch ----
    const int rg0 = b * Lq + q0 + 16*w + g;         // global row
    float* Op0 = g_Opart + ((size_t)c * R + rg0) * DH;
    float* Op1 = Op0 + (size_t)8 * DH;
    if (tg == 0){
        g_lpart[(size_t)c * R + rg0]     = lsum0;
        g_lpart[(size_t)c * R + rg0 + 8] = lsum1;
    }
    #pragma unroll
    for (int nt = 0; nt < 8; nt++){
        float2 a0, a1;
        a0.x = oc[nt][0]; a0.y = oc[nt][1];
        a1.x = oc[nt][2]; a1.y = oc[nt][3];
        *(float2*)(Op0 + nt*8 + 2*tg) = a0;
        *(float2*)(Op1 + nt*8 + 2*tg) = a1;
    }
}

// ---------------- Phase 2: combine chunk partials + normalize ----------------
__global__ __launch_bounds__(256, 8)
void fa_combine_kernel(const int* __restrict__ vlen, float* __restrict__ O,
                       int Lq, int Lk, int B, int ck)
{
    const int idx = blockIdx.x * blockDim.x + threadIdx.x;
    const int total = B * Lq * (DH / 4);
    if (idx >= total) return;

    const int rd = idx >> 4;        // global row (b*Lq + q)
    const int d4 = idx & 15;
    const int b  = rd / Lq;
    const int R  = B * Lq;

    int vl = vlen[b];
    if (vl < 1) vl = 1;
    if (vl > Lk) vl = Lk;
    const int nact = (vl + ck - 1) / ck;

    float4 acc = make_float4(0.f, 0.f, 0.f, 0.f);
    float l = 0.f;
    for (int c = 0; c < nact; c++){
        const float4 p = *(const float4*)(g_Opart + ((size_t)c * R + rd) * DH + d4 * 4);
        acc.x += p.x; acc.y += p.y; acc.z += p.z; acc.w += p.w;
        l += g_lpart[(size_t)c * R + rd];
    }
    const float inv = 1.f / l;
    acc.x *= inv; acc.y *= inv; acc.z *= inv; acc.w *= inv;
    *(float4*)(O + (size_t)rd * DH + d4 * 4) = acc;
}

extern "C" void kernel_launch(void* const* d_in, const int* in_sizes, int n_in,
                              void* d_out, int out_size)
{
    const float* Q  = (const float*)d_in[0];
    const float* K  = (const float*)d_in[1];
    const float* V  = (const float*)d_in[2];
    const int*   vl = (const int*)d_in[3];
    float*       O  = (float*)d_out;

    const int B  = in_sizes[3];
    const int Lq = in_sizes[0] / (B * DH);
    const int Lk = in_sizes[1] / (B * DH);

    // chunk size: multiple of BN, at most NCH_MAX chunks
    int ck = ((Lk + NCH_MAX * BN - 1) / (NCH_MAX * BN)) * BN;
    if (ck < BN) ck = BN;
    const int nch = (Lk + ck - 1) / ck;

    cudaFuncSetAttribute(fa_part_kernel,
                         cudaFuncAttributeMaxDynamicSharedMemorySize, SM_TOTAL);

    dim3 grid1(Lq / BM, B, nch);
    fa_part_kernel<<<grid1, 256, SM_TOTAL>>>(Q, K, V, vl, Lq, Lk, ck);

    const int total = B * Lq * (DH / 4);
    fa_combine_kernel<<<(total + 255) / 256, 256>>>(vl, O, Lq, Lk, B, ck);
}